// round 1
// baseline (speedup 1.0000x reference)
#include <cuda_runtime.h>

// YOLO loss: pred [8192, 49*30] f32, target [8192, 49*25] f32 -> scalar f32.
// M = 8192*49 = 401408 cells. One thread per cell, 128 cells per block,
// coalesced float4 staging through shared memory, deterministic 2-kernel
// reduction (block partials in a __device__ global, then one reduce block).

#define YS        7
#define YS2       49
#define YB_P      30          // 5*B + C = 30 floats per cell (pred)
#define YB_T      25          // 5 + C   = 25 floats per cell (target)
#define CELLS     128         // cells (=threads) per block
#define NCELLS    401408      // 8192 * 49
#define NBLOCKS   3136        // NCELLS / CELLS (exact)
#define NBATCH    8192.0

__device__ double g_partials[NBLOCKS];

__global__ __launch_bounds__(CELLS) void yolo_loss_kernel(
    const float* __restrict__ pred, const float* __restrict__ tgt)
{
    __shared__ float sp[CELLS * YB_P];   // 15360 B
    __shared__ float st[CELLS * YB_T];   // 12800 B

    const int b   = blockIdx.x;
    const int tid = threadIdx.x;

    // ---- coalesced float4 staging ----
    {
        const float4* gp = (const float4*)(pred + (size_t)b * CELLS * YB_P);
        float4* s4 = (float4*)sp;
        #pragma unroll 2
        for (int i = tid; i < CELLS * YB_P / 4; i += CELLS) s4[i] = gp[i];

        const float4* gt = (const float4*)(tgt + (size_t)b * CELLS * YB_T);
        float4* t4 = (float4*)st;
        #pragma unroll 2
        for (int i = tid; i < CELLS * YB_T / 4; i += CELLS) t4[i] = gt[i];
    }
    __syncthreads();

    // ---- per-cell loss ----
    const float* pc = sp + tid * YB_P;
    const float* tc = st + tid * YB_T;

    const int cell = b * CELLS + tid;
    const int g    = cell % YS2;
    const float gy = (float)(g / YS);
    const float gx = (float)(g % YS);

    const float t0    = tc[0];
    const float objf  = (t0 == 1.0f) ? 1.0f : 0.0f;
    const float noobf = (t0 == 0.0f) ? 1.0f : 0.0f;

    // target box -> xyxy (w,h NOT divided by S, matching reference)
    const float tx = tc[1], ty = tc[2], tw = tc[3], th = tc[4];
    const float tcx = (gx + tx) / 7.0f;
    const float tcy = (gy + ty) / 7.0f;
    const float tx1 = tcx - tw * 0.5f, ty1 = tcy - th * 0.5f;
    const float tx2 = tcx + tw * 0.5f, ty2 = tcy + th * 0.5f;
    const float area_t = (tx2 - tx1) * (ty2 - ty1);

    float iou0, iou1;
    #pragma unroll
    for (int bb = 0; bb < 2; bb++) {
        const float px = fabsf(pc[bb * 5 + 1]);
        const float py = fabsf(pc[bb * 5 + 2]);
        const float pw = fabsf(pc[bb * 5 + 3]);
        const float ph = fabsf(pc[bb * 5 + 4]);
        const float cx = (gx + px) / 7.0f;
        const float cy = (gy + py) / 7.0f;
        const float x1 = cx - pw * 0.5f, y1 = cy - ph * 0.5f;
        const float x2 = cx + pw * 0.5f, y2 = cy + ph * 0.5f;
        const float ltx = fmaxf(x1, tx1), lty = fmaxf(y1, ty1);
        const float rbx = fminf(x2, tx2), rby = fminf(y2, ty2);
        const float iw  = fmaxf(rbx - ltx, 0.0f);
        const float ih  = fmaxf(rby - lty, 0.0f);
        const float inter  = iw * ih;
        const float area_p = (x2 - x1) * (y2 - y1);
        const float v = inter / (area_p + area_t - inter);
        if (bb == 0) iou0 = v; else iou1 = v;
    }

    // argmax with tie -> box 0 (jnp.argmax picks first occurrence)
    const int   best    = (iou1 > iou0) ? 1 : 0;
    const float max_iou = best ? iou1 : iou0;
    const float* rb = pc + best * 5;

    const float dx = rb[1] - tx;
    const float dy = rb[2] - ty;
    const float xy_loss = dx * dx + dy * dy;

    const float swd = sqrtf(fabsf(rb[3])) - sqrtf(fabsf(tw));
    const float shd = sqrtf(fabsf(rb[4])) - sqrtf(fabsf(th));
    const float wh_loss = swd * swd + shd * shd;

    const float doc = rb[0] - max_iou;
    const float obj_conf = doc * doc;

    const float noobj_conf = 0.5f * (pc[0] * pc[0] + pc[5] * pc[5]);

    float cls = 0.0f;
    #pragma unroll
    for (int k = 0; k < 20; k++) {
        const float d = pc[10 + k] - tc[5 + k];
        cls += d * d;
    }

    float loss = objf * (5.0f * (xy_loss + wh_loss) + obj_conf + cls)
               + noobf * noobj_conf;

    // ---- deterministic block reduction ----
    #pragma unroll
    for (int o = 16; o > 0; o >>= 1)
        loss += __shfl_down_sync(0xffffffffu, loss, o);

    __shared__ float wsum[CELLS / 32];
    const int lane = tid & 31;
    const int wrp  = tid >> 5;
    if (lane == 0) wsum[wrp] = loss;
    __syncthreads();
    if (tid == 0) {
        double s = 0.0;
        #pragma unroll
        for (int w = 0; w < CELLS / 32; w++) s += (double)wsum[w];
        g_partials[b] = s;
    }
}

__global__ __launch_bounds__(1024) void yolo_reduce_kernel(float* __restrict__ out)
{
    __shared__ double sm[32];
    double s = 0.0;
    for (int i = threadIdx.x; i < NBLOCKS; i += 1024)
        s += g_partials[i];

    #pragma unroll
    for (int o = 16; o > 0; o >>= 1)
        s += __shfl_down_sync(0xffffffffu, s, o);

    const int lane = threadIdx.x & 31;
    const int wrp  = threadIdx.x >> 5;
    if (lane == 0) sm[wrp] = s;
    __syncthreads();
    if (threadIdx.x < 32) {
        double v = (threadIdx.x < 32) ? sm[threadIdx.x] : 0.0;
        #pragma unroll
        for (int o = 16; o > 0; o >>= 1)
            v += __shfl_down_sync(0xffffffffu, v, o);
        if (threadIdx.x == 0) out[0] = (float)(v / NBATCH);
    }
}

extern "C" void kernel_launch(void* const* d_in, const int* in_sizes, int n_in,
                              void* d_out, int out_size)
{
    const float* pred = (const float*)d_in[0];
    const float* tgt  = (const float*)d_in[1];
    float* out        = (float*)d_out;

    yolo_loss_kernel<<<NBLOCKS, CELLS>>>(pred, tgt);
    yolo_reduce_kernel<<<1, 1024>>>(out);
}

// round 2
// speedup vs baseline: 1.0863x; 1.0863x over previous
#include <cuda_runtime.h>

// YOLO loss, fused single-kernel version.
// pred [8192, 49*30] f32, target [8192, 49*25] f32 -> scalar f32.
// M = 401408 cells. 784 blocks x 128 threads, 4 tiles of 128 cells per block.
// Per-thread register accumulation across tiles, one block reduction,
// last-block-done final reduction (threadfence + ticket), no second launch.

#define YS2       49
#define YB_P      30          // floats per cell (pred)
#define YB_T      25          // floats per cell (target)
#define CELLS     128         // cells per tile (= threads per block)
#define TILES     4           // tiles per block
#define NBLOCKS   784         // 401408 / (128*4)
#define NBATCH    8192.0

__device__ double       g_partials[NBLOCKS];
__device__ unsigned int g_ticket;          // zero-initialized; reset by last block

__global__ __launch_bounds__(CELLS) void yolo_loss_kernel(
    const float* __restrict__ pred, const float* __restrict__ tgt,
    float* __restrict__ out)
{
    __shared__ float  sp[CELLS * YB_P];    // 15360 B
    __shared__ float  st[CELLS * YB_T];    // 12800 B
    __shared__ float  wsum[CELLS / 32];
    __shared__ int    s_last;

    const int b   = blockIdx.x;
    const int tid = threadIdx.x;

    float acc = 0.0f;

    for (int t = 0; t < TILES; t++) {
        const int tile = b * TILES + t;

        // ---- coalesced float4 staging ----
        {
            const float4* gp = (const float4*)(pred + (size_t)tile * CELLS * YB_P);
            float4* s4 = (float4*)sp;
            #pragma unroll
            for (int i = tid; i < CELLS * YB_P / 4; i += CELLS) s4[i] = gp[i];

            const float4* gt = (const float4*)(tgt + (size_t)tile * CELLS * YB_T);
            float4* t4 = (float4*)st;
            #pragma unroll
            for (int i = tid; i < CELLS * YB_T / 4; i += CELLS) t4[i] = gt[i];
        }
        __syncthreads();

        // ---- per-cell loss ----
        const float* pc = sp + tid * YB_P;
        const float* tc = st + tid * YB_T;

        const int cell = tile * CELLS + tid;
        const int g    = cell % YS2;
        const float gy = (float)(g / 7);
        const float gx = (float)(g % 7);

        const float t0    = tc[0];
        const float objf  = (t0 == 1.0f) ? 1.0f : 0.0f;
        const float noobf = (t0 == 0.0f) ? 1.0f : 0.0f;

        const float tx = tc[1], ty = tc[2], tw = tc[3], th = tc[4];
        const float tcx = (gx + tx) / 7.0f;
        const float tcy = (gy + ty) / 7.0f;
        const float tx1 = tcx - tw * 0.5f, ty1 = tcy - th * 0.5f;
        const float tx2 = tcx + tw * 0.5f, ty2 = tcy + th * 0.5f;
        const float area_t = (tx2 - tx1) * (ty2 - ty1);

        float iou0, iou1;
        #pragma unroll
        for (int bb = 0; bb < 2; bb++) {
            const float px = fabsf(pc[bb * 5 + 1]);
            const float py = fabsf(pc[bb * 5 + 2]);
            const float pw = fabsf(pc[bb * 5 + 3]);
            const float ph = fabsf(pc[bb * 5 + 4]);
            const float cx = (gx + px) / 7.0f;
            const float cy = (gy + py) / 7.0f;
            const float x1 = cx - pw * 0.5f, y1 = cy - ph * 0.5f;
            const float x2 = cx + pw * 0.5f, y2 = cy + ph * 0.5f;
            const float ltx = fmaxf(x1, tx1), lty = fmaxf(y1, ty1);
            const float rbx = fminf(x2, tx2), rby = fminf(y2, ty2);
            const float iw  = fmaxf(rbx - ltx, 0.0f);
            const float ih  = fmaxf(rby - lty, 0.0f);
            const float inter  = iw * ih;
            const float area_p = (x2 - x1) * (y2 - y1);
            const float v = inter / (area_p + area_t - inter);
            if (bb == 0) iou0 = v; else iou1 = v;
        }

        const int   best    = (iou1 > iou0) ? 1 : 0;
        const float max_iou = best ? iou1 : iou0;
        const float* rb = pc + best * 5;

        const float dx = rb[1] - tx;
        const float dy = rb[2] - ty;
        const float xy_loss = dx * dx + dy * dy;

        const float swd = sqrtf(fabsf(rb[3])) - sqrtf(fabsf(tw));
        const float shd = sqrtf(fabsf(rb[4])) - sqrtf(fabsf(th));
        const float wh_loss = swd * swd + shd * shd;

        const float doc = rb[0] - max_iou;
        const float obj_conf = doc * doc;

        const float noobj_conf = 0.5f * (pc[0] * pc[0] + pc[5] * pc[5]);

        float cls = 0.0f;
        #pragma unroll
        for (int k = 0; k < 20; k++) {
            const float d = pc[10 + k] - tc[5 + k];
            cls += d * d;
        }

        acc += objf * (5.0f * (xy_loss + wh_loss) + obj_conf + cls)
             + noobf * noobj_conf;

        __syncthreads();   // protect smem before next tile's staging
    }

    // ---- deterministic block reduction (float -> double partial) ----
    #pragma unroll
    for (int o = 16; o > 0; o >>= 1)
        acc += __shfl_down_sync(0xffffffffu, acc, o);

    const int lane = tid & 31;
    const int wrp  = tid >> 5;
    if (lane == 0) wsum[wrp] = acc;
    __syncthreads();

    if (tid == 0) {
        double s = 0.0;
        #pragma unroll
        for (int w = 0; w < CELLS / 32; w++) s += (double)wsum[w];
        g_partials[b] = s;
        __threadfence();
        unsigned int ticket = atomicAdd(&g_ticket, 1u);
        s_last = (ticket == NBLOCKS - 1u) ? 1 : 0;
    }
    __syncthreads();

    // ---- last block: final reduction over all partials ----
    if (s_last) {
        __threadfence();
        __shared__ double dsum[CELLS / 32];

        double s = 0.0;
        #pragma unroll
        for (int i = tid; i < NBLOCKS; i += CELLS)
            s += g_partials[i];

        #pragma unroll
        for (int o = 16; o > 0; o >>= 1)
            s += __shfl_down_sync(0xffffffffu, s, o);

        if (lane == 0) dsum[wrp] = s;
        __syncthreads();

        if (tid == 0) {
            double total = 0.0;
            #pragma unroll
            for (int w = 0; w < CELLS / 32; w++) total += dsum[w];
            out[0] = (float)(total / NBATCH);
            g_ticket = 0;   // reset for next graph replay
        }
    }
}

extern "C" void kernel_launch(void* const* d_in, const int* in_sizes, int n_in,
                              void* d_out, int out_size)
{
    const float* pred = (const float*)d_in[0];
    const float* tgt  = (const float*)d_in[1];
    float* out        = (float*)d_out;

    yolo_loss_kernel<<<NBLOCKS, CELLS>>>(pred, tgt, out);
}